// round 3
// baseline (speedup 1.0000x reference)
#include <cuda_runtime.h>

// NearestEmbed (VQ): x [32,64,64,64] f32, emb [64,1024] f32
// out = [ result (32*64*64*64 f32) | argmin (32*64*64 as f32, if room) ]

typedef unsigned long long ull;

#define B_    32
#define D_    64
#define K_    1024
#define HW_   4096                 // 64*64
#define NPTS  (B_*HW_)             // 131072 rows
#define RES_ELEMS (B_*D_*HW_)      // 8388608

#define KT    128                  // codes per smem tile
#define EPAD  68                   // padded row stride (floats): 4-way STS conflict, 16B aligned
#define NT    256                  // threads per block

__device__ __forceinline__ ull pack2f(float lo, float hi) {
    ull r; asm("mov.b64 %0, {%1, %2};" : "=l"(r) : "f"(lo), "f"(hi)); return r;
}
__device__ __forceinline__ void ffma2(ull& d, ull a, ull b) {
    asm("fma.rn.f32x2 %0, %1, %2, %0;" : "+l"(d) : "l"(a), "l"(b));
}
__device__ __forceinline__ ull fadd2(ull a, ull b) {
    ull r; asm("add.rn.f32x2 %0, %1, %2;" : "=l"(r) : "l"(a), "l"(b)); return r;
}
__device__ __forceinline__ void unpack2f(ull v, float& lo, float& hi) {
    asm("mov.b64 {%0, %1}, %2;" : "=f"(lo), "=f"(hi) : "l"(v));
}

__global__ __launch_bounds__(NT, 2)
void vq_argmin_kernel(const float* __restrict__ x,
                      const float* __restrict__ emb,
                      float* __restrict__ out, int out_size)
{
    __shared__ __align__(16) float se[KT * EPAD];  // 34816 B, [code][dim]
    __shared__ float ssq[KT];
    __shared__ float sp[NT];

    const int t   = threadIdx.x;
    const int n   = blockIdx.x * NT + t;           // point id = b*HW + h*W + w
    const int b   = n >> 12;                       // / 4096
    const int rem = n & 4095;
    const float* xp = x + b * (D_ * HW_) + rem;    // x[b, d, h, w] = xp[d*HW_]

    // Load the D=64 x-values for this point, packed as 32 f32x2 pairs.
    // Coalesced across threads (consecutive rem) for each d.
    ull xr[32];
#pragma unroll
    for (int j = 0; j < 32; ++j) {
        float a = xp[(2 * j)     * HW_];
        float c = xp[(2 * j + 1) * HW_];
        xr[j] = pack2f(a, c);
    }

    float best = 3.402823e38f;
    int   bidx = 0;

    const int kk = t & (KT - 1);   // code this thread fills
    const int dh = t >> 7;         // 0/1: which parity of d this thread fills

    for (int tile = 0; tile < K_ / KT; ++tile) {
        const int k0 = tile * KT;
        __syncthreads();           // previous tile's compute done before overwrite

        // Fill smem tile [code][dim] and accumulate ||e||^2 partials for free.
        float ss = 0.f;
#pragma unroll
        for (int i = 0; i < 32; ++i) {
            int d = 2 * i + dh;
            float v = emb[d * K_ + k0 + kk];       // coalesced along k
            se[kk * EPAD + d] = v;                 // 4-way bank conflict, amortized
            ss = fmaf(v, v, ss);
        }
        sp[t] = ss;
        __syncthreads();
        if (t < KT) ssq[t] = sp[t] + sp[t + KT];
        __syncthreads();

        // Scan 128 codes: s_k = ||e_k||^2 - 2 * x.e_k  (x.x constant, dropped)
#pragma unroll 2
        for (int k = 0; k < KT; ++k) {
            // same address across all threads -> smem broadcast, conflict-free
            const ulonglong2* ep = reinterpret_cast<const ulonglong2*>(se + k * EPAD);
            ull a0 = 0, a1 = 0, a2 = 0, a3 = 0;
#pragma unroll
            for (int j = 0; j < 16; j += 4) {
                ulonglong2 e0 = ep[j + 0];
                ulonglong2 e1 = ep[j + 1];
                ulonglong2 e2 = ep[j + 2];
                ulonglong2 e3 = ep[j + 3];
                ffma2(a0, xr[2 * j + 0], e0.x);
                ffma2(a1, xr[2 * j + 1], e0.y);
                ffma2(a2, xr[2 * j + 2], e1.x);
                ffma2(a3, xr[2 * j + 3], e1.y);
                ffma2(a0, xr[2 * j + 4], e2.x);
                ffma2(a1, xr[2 * j + 5], e2.y);
                ffma2(a2, xr[2 * j + 6], e3.x);
                ffma2(a3, xr[2 * j + 7], e3.y);
            }
            ull s01 = fadd2(a0, a1);
            ull s23 = fadd2(a2, a3);
            ull s   = fadd2(s01, s23);
            float lo, hi; unpack2f(s, lo, hi);
            float dot  = lo + hi;
            float dist = fmaf(-2.f, dot, ssq[k]);
            if (dist < best) { best = dist; bidx = k0 + k; }  // strict '<': first-index ties, matches jnp.argmin
        }
    }

    // Epilogue: gather the winning code vector (emb hot in L2) and scatter to NCHW.
    const int base = b * (D_ * HW_) + rem;
#pragma unroll
    for (int d = 0; d < D_; ++d) {
        out[base + d * HW_] = __ldg(&emb[d * K_ + bidx]);
    }
    // Second tuple output: argmin indices, row-major [B,H,W] == point order n.
    if (out_size >= RES_ELEMS + NPTS)
        out[RES_ELEMS + n] = (float)bidx;
}

extern "C" void kernel_launch(void* const* d_in, const int* in_sizes, int n_in,
                              void* d_out, int out_size)
{
    const float* x   = (const float*)d_in[0];
    const float* emb = (const float*)d_in[1];
    // Robustness: identify tensors by element count in case of input-order surprises.
    if (n_in >= 2 && in_sizes[0] == D_ * K_ && in_sizes[1] == RES_ELEMS) {
        x   = (const float*)d_in[1];
        emb = (const float*)d_in[0];
    }
    vq_argmin_kernel<<<NPTS / NT, NT>>>(x, emb, (float*)d_out, out_size);
}

// round 4
// speedup vs baseline: 1.3034x; 1.3034x over previous
#include <cuda_runtime.h>

// NearestEmbed (VQ): x [32,64,64,64] f32, emb [64,1024] f32
// out = [ result (32*64*64*64 f32) | argmin (32*64*64 as f32, if room) ]
// R3: 2 points per thread -> halve LDS traffic per FMA (L1 pipe was binding at 80.6%).

typedef unsigned long long ull;

#define B_    32
#define D_    64
#define K_    1024
#define HW_   4096
#define NPTS  (B_*HW_)             // 131072
#define RES_ELEMS (B_*D_*HW_)      // 8388608

#define KT    128                  // codes per smem tile
#define EPAD  68                   // padded row stride (floats)
#define NT    256                  // threads per block
#define PPT   2                    // points per thread

__device__ __forceinline__ ull pack2f(float lo, float hi) {
    ull r; asm("mov.b64 %0, {%1, %2};" : "=l"(r) : "f"(lo), "f"(hi)); return r;
}
__device__ __forceinline__ void ffma2(ull& d, ull a, ull b) {
    asm("fma.rn.f32x2 %0, %1, %2, %0;" : "+l"(d) : "l"(a), "l"(b));
}
__device__ __forceinline__ ull fadd2(ull a, ull b) {
    ull r; asm("add.rn.f32x2 %0, %1, %2;" : "=l"(r) : "l"(a), "l"(b)); return r;
}
__device__ __forceinline__ void unpack2f(ull v, float& lo, float& hi) {
    asm("mov.b64 {%0, %1}, %2;" : "=f"(lo), "=f"(hi) : "l"(v));
}

__global__ __launch_bounds__(NT, 1)
void vq_argmin_kernel(const float* __restrict__ x,
                      const float* __restrict__ emb,
                      float* __restrict__ out, int out_size)
{
    __shared__ __align__(16) float se[KT * EPAD];  // [code][dim], 34816 B
    __shared__ float ssq[KT];
    __shared__ float sp[NT];

    const int t  = threadIdx.x;
    const int n0 = blockIdx.x * (NT * PPT) + t;    // point 0
    const int n1 = n0 + NT;                        // point 1 (same 512-block, same batch)

    const int b0 = n0 >> 12, r0 = n0 & 4095;
    const int b1 = n1 >> 12, r1 = n1 & 4095;
    const float* xp0 = x + b0 * (D_ * HW_) + r0;
    const float* xp1 = x + b1 * (D_ * HW_) + r1;

    // x for both points, packed as f32x2 pairs along D. Coalesced loads.
    ull xr0[32], xr1[32];
#pragma unroll
    for (int j = 0; j < 32; ++j) {
        xr0[j] = pack2f(xp0[(2 * j) * HW_], xp0[(2 * j + 1) * HW_]);
        xr1[j] = pack2f(xp1[(2 * j) * HW_], xp1[(2 * j + 1) * HW_]);
    }

    float best0 = 3.402823e38f, best1 = 3.402823e38f;
    int   idx0 = 0, idx1 = 0;

    const int kk = t & (KT - 1);   // code row this thread fills
    const int dh = t >> 7;         // d-parity this thread fills

    for (int tile = 0; tile < K_ / KT; ++tile) {
        const int k0 = tile * KT;
        __syncthreads();

        // Fill e-tile [code][dim]; accumulate ||e||^2 partials for free.
        float ss = 0.f;
#pragma unroll
        for (int i = 0; i < 32; ++i) {
            int d = 2 * i + dh;
            float v = emb[d * K_ + k0 + kk];
            se[kk * EPAD + d] = v;
            ss = fmaf(v, v, ss);
        }
        sp[t] = ss;
        __syncthreads();
        if (t < KT) ssq[t] = sp[t] + sp[t + KT];
        __syncthreads();

        // Scan codes: each loaded e-operand feeds BOTH points (LDS amortized 2x).
#pragma unroll 2
        for (int k = 0; k < KT; ++k) {
            const ulonglong2* ep = reinterpret_cast<const ulonglong2*>(se + k * EPAD);
            ull p0a = 0, p0b = 0, p1a = 0, p1b = 0;   // 2 chains/pt -> 4 indep chains
#pragma unroll
            for (int j = 0; j < 16; j += 2) {
                ulonglong2 e0 = ep[j];
                ulonglong2 e1 = ep[j + 1];
                ffma2(p0a, xr0[2 * j + 0], e0.x);
                ffma2(p1a, xr1[2 * j + 0], e0.x);
                ffma2(p0b, xr0[2 * j + 1], e0.y);
                ffma2(p1b, xr1[2 * j + 1], e0.y);
                ffma2(p0a, xr0[2 * j + 2], e1.x);
                ffma2(p1a, xr1[2 * j + 2], e1.x);
                ffma2(p0b, xr0[2 * j + 3], e1.y);
                ffma2(p1b, xr1[2 * j + 3], e1.y);
            }
            float lo, hi;
            ull s0 = fadd2(p0a, p0b);
            unpack2f(s0, lo, hi);
            float dist0 = fmaf(-2.f, lo + hi, ssq[k]);
            ull s1 = fadd2(p1a, p1b);
            unpack2f(s1, lo, hi);
            float dist1 = fmaf(-2.f, lo + hi, ssq[k]);
            if (dist0 < best0) { best0 = dist0; idx0 = k0 + k; }  // strict '<': first-index ties
            if (dist1 < best1) { best1 = dist1; idx1 = k0 + k; }
        }
    }

    // Epilogue: gather winning code vectors (emb L2-hot), scatter to NCHW.
    const int base0 = b0 * (D_ * HW_) + r0;
    const int base1 = b1 * (D_ * HW_) + r1;
#pragma unroll
    for (int d = 0; d < D_; ++d) {
        out[base0 + d * HW_] = __ldg(&emb[d * K_ + idx0]);
        out[base1 + d * HW_] = __ldg(&emb[d * K_ + idx1]);
    }
    if (out_size >= RES_ELEMS + NPTS) {
        out[RES_ELEMS + n0] = (float)idx0;
        out[RES_ELEMS + n1] = (float)idx1;
    }
}

extern "C" void kernel_launch(void* const* d_in, const int* in_sizes, int n_in,
                              void* d_out, int out_size)
{
    const float* x   = (const float*)d_in[0];
    const float* emb = (const float*)d_in[1];
    if (n_in >= 2 && in_sizes[0] == D_ * K_ && in_sizes[1] == RES_ELEMS) {
        x   = (const float*)d_in[1];
        emb = (const float*)d_in[0];
    }
    vq_argmin_kernel<<<NPTS / (NT * PPT), NT>>>(x, emb, (float*)d_out, out_size);
}

// round 5
// speedup vs baseline: 1.3496x; 1.0355x over previous
#include <cuda_runtime.h>

// NearestEmbed (VQ): x [32,64,64,64] f32, emb [64,1024] f32
// out = [ result (8388608 f32) | argmin (131072 as f32, if room) ]
// R5: 4pt x 4code register blocking, x+e both in smem, 2 CTAs/SM for latency hiding.

typedef unsigned long long ull;

#define B_    32
#define D_    64
#define K_    1024
#define HW_   4096
#define NPTS  (B_*HW_)             // 131072
#define RES_ELEMS (B_*D_*HW_)      // 8388608

#define NT     256
#define PT_BLK 128                 // points per block
#define KT     32                  // codes per e-tile
#define XROW   68                  // floats per row (272B = 17x16B, odd -> conflict-free LDS.128)
#define EROW   68

__device__ __forceinline__ void ffma2(ull& d, ull a, ull b) {
    asm("fma.rn.f32x2 %0, %1, %2, %0;" : "+l"(d) : "l"(a), "l"(b));
}
__device__ __forceinline__ void unpack2f(ull v, float& lo, float& hi) {
    asm("mov.b64 {%0, %1}, %2;" : "=f"(lo), "=f"(hi) : "l"(v));
}

__global__ __launch_bounds__(NT, 2)
void vq_kernel(const float* __restrict__ x, const float* __restrict__ emb,
               float* __restrict__ out, int out_size)
{
    __shared__ __align__(16) float xs[PT_BLK * XROW];  // 34816 B
    __shared__ __align__(16) float es[KT * EROW];      //  8704 B
    __shared__ float ssq[KT];
    __shared__ float sp[NT];
    __shared__ int   sidx[PT_BLK];

    const int t  = threadIdx.x;
    const int pg = t >> 3;    // 0..31 : owns points pg + 32*i
    const int cg = t & 7;     // 0..7  : owns codes  cg + 8*j (per tile)

    const int n0   = blockIdx.x * PT_BLK;  // 128 | 4096 -> whole block in one batch b
    const int bb   = n0 >> 12;
    const int rem0 = n0 & 4095;
    const float* xblk = x + bb * (D_ * HW_) + rem0;

    // ---- x-tile fill: 128 pts x 64 d, coalesced LDG (fixed d, consecutive p) ----
#pragma unroll 4
    for (int i = 0; i < 32; ++i) {
        int flat = t + NT * i;             // 0..8191
        int p = flat & 127, d = flat >> 7;
        xs[p * XROW + d] = xblk[d * HW_ + p];
    }

    float best[4] = {3.402823e38f, 3.402823e38f, 3.402823e38f, 3.402823e38f};
    int   bidx[4] = {0, 0, 0, 0};

    for (int tile = 0; tile < K_ / KT; ++tile) {
        const int k0 = tile * KT;
        __syncthreads();   // consumers done with es (covers x-fill on first pass)

        // ---- e-tile fill + ||e||^2 partials (coalesced along k) ----
        {
            const int kk = t & 31, dg = t >> 5;      // code, d-octet
            float ss = 0.f;
            const float* epp = emb + (dg * 8) * K_ + k0 + kk;
            float* esp = es + kk * EROW + dg * 8;
#pragma unroll
            for (int j = 0; j < 8; ++j) {
                float v = epp[j * K_];
                esp[j] = v;
                ss = fmaf(v, v, ss);
            }
            sp[t] = ss;
        }
        __syncthreads();
        if (t < KT) {
            float s = 0.f;
#pragma unroll
            for (int i = 0; i < 8; ++i) s += sp[t + 32 * i];
            ssq[t] = s;
        }
        __syncthreads();

        // ---- 4x4 register block over 16 d-chunks (4 dims each) ----
        ull acc[16];
#pragma unroll
        for (int i = 0; i < 16; ++i) acc[i] = 0ull;

        const ulonglong2* xr = (const ulonglong2*)(xs + pg * XROW); // + 544*i per pt
        const ulonglong2* er = (const ulonglong2*)(es + cg * EROW); // + 136*j per code

#pragma unroll
        for (int c = 0; c < 16; ++c) {
            ulonglong2 xa0 = xr[c];
            ulonglong2 xa1 = xr[c + 1 * (32 * XROW / 4)];
            ulonglong2 xa2 = xr[c + 2 * (32 * XROW / 4)];
            ulonglong2 xa3 = xr[c + 3 * (32 * XROW / 4)];
            ulonglong2 ea0 = er[c];
            ulonglong2 ea1 = er[c + 1 * (8 * EROW / 4)];
            ulonglong2 ea2 = er[c + 2 * (8 * EROW / 4)];
            ulonglong2 ea3 = er[c + 3 * (8 * EROW / 4)];

            ffma2(acc[ 0], xa0.x, ea0.x); ffma2(acc[ 1], xa0.x, ea1.x);
            ffma2(acc[ 2], xa0.x, ea2.x); ffma2(acc[ 3], xa0.x, ea3.x);
            ffma2(acc[ 4], xa1.x, ea0.x); ffma2(acc[ 5], xa1.x, ea1.x);
            ffma2(acc[ 6], xa1.x, ea2.x); ffma2(acc[ 7], xa1.x, ea3.x);
            ffma2(acc[ 8], xa2.x, ea0.x); ffma2(acc[ 9], xa2.x, ea1.x);
            ffma2(acc[10], xa2.x, ea2.x); ffma2(acc[11], xa2.x, ea3.x);
            ffma2(acc[12], xa3.x, ea0.x); ffma2(acc[13], xa3.x, ea1.x);
            ffma2(acc[14], xa3.x, ea2.x); ffma2(acc[15], xa3.x, ea3.x);
            ffma2(acc[ 0], xa0.y, ea0.y); ffma2(acc[ 1], xa0.y, ea1.y);
            ffma2(acc[ 2], xa0.y, ea2.y); ffma2(acc[ 3], xa0.y, ea3.y);
            ffma2(acc[ 4], xa1.y, ea0.y); ffma2(acc[ 5], xa1.y, ea1.y);
            ffma2(acc[ 6], xa1.y, ea2.y); ffma2(acc[ 7], xa1.y, ea3.y);
            ffma2(acc[ 8], xa2.y, ea0.y); ffma2(acc[ 9], xa2.y, ea1.y);
            ffma2(acc[10], xa2.y, ea2.y); ffma2(acc[11], xa2.y, ea3.y);
            ffma2(acc[12], xa3.y, ea0.y); ffma2(acc[13], xa3.y, ea1.y);
            ffma2(acc[14], xa3.y, ea2.y); ffma2(acc[15], xa3.y, ea3.y);
        }

        // ---- finalize tile: dist = ||e||^2 - 2 x.e ; strict '<' keeps first idx ----
#pragma unroll
        for (int j = 0; j < 4; ++j) {
            const float sq = ssq[cg + 8 * j];
            const int   kg = k0 + cg + 8 * j;
#pragma unroll
            for (int i = 0; i < 4; ++i) {
                float lo, hi; unpack2f(acc[4 * i + j], lo, hi);
                float dist = fmaf(-2.f, lo + hi, sq);
                if (dist < best[i]) { best[i] = dist; bidx[i] = kg; }
            }
        }
    }

    // ---- argmin across the 8 code-groups sharing each point (width-8 butterfly) ----
#pragma unroll
    for (int i = 0; i < 4; ++i) {
        float d = best[i]; int ix = bidx[i];
#pragma unroll
        for (int w = 4; w > 0; w >>= 1) {
            float d2 = __shfl_xor_sync(0xffffffffu, d,  w, 8);
            int   i2 = __shfl_xor_sync(0xffffffffu, ix, w, 8);
            if (d2 < d || (d2 == d && i2 < ix)) { d = d2; ix = i2; }
        }
        best[i] = d; bidx[i] = ix;
    }

    if (cg == 0) {
#pragma unroll
        for (int i = 0; i < 4; ++i) sidx[pg + 32 * i] = bidx[i];
    }
    if (cg == 1 && out_size >= RES_ELEMS + NPTS) {
#pragma unroll
        for (int i = 0; i < 4; ++i)
            out[RES_ELEMS + n0 + pg + 32 * i] = (float)bidx[i];
    }
    __syncthreads();

    // ---- gather winning code vectors (emb L2-hot), coalesced stores ----
    float* ob = out + bb * (D_ * HW_) + rem0;
#pragma unroll 4
    for (int i = 0; i < 32; ++i) {
        int flat = t + NT * i;
        int p = flat & 127, d = flat >> 7;
        ob[d * HW_ + p] = __ldg(&emb[d * K_ + sidx[p]]);
    }
}

extern "C" void kernel_launch(void* const* d_in, const int* in_sizes, int n_in,
                              void* d_out, int out_size)
{
    const float* x   = (const float*)d_in[0];
    const float* emb = (const float*)d_in[1];
    if (n_in >= 2 && in_sizes[0] == D_ * K_ && in_sizes[1] == RES_ELEMS) {
        x   = (const float*)d_in[1];
        emb = (const float*)d_in[0];
    }
    vq_kernel<<<NPTS / PT_BLK, NT>>>(x, emb, (float*)d_out, out_size);
}

// round 7
// speedup vs baseline: 2.2908x; 1.6974x over previous
#include <cuda_runtime.h>
#include <cstdint>

// NearestEmbed (VQ) via 3xTF32 mma.sync (base-target PTX; tcgen05 unavailable:
// harness compiles for compute_103, not sm_103a).
// x [32,64,64,64] f32, emb [64,1024] f32
// out = [ result (8388608 f32) | argmin (131072 as f32, if room) ]

typedef uint32_t u32;

#define B_    32
#define D_    64
#define K_    1024
#define HW_   4096
#define NPTS  (B_*HW_)
#define RES_ELEMS (B_*D_*HW_)

#define NT     256
#define PT     128                 // points per block
#define KTILE  64                  // codes per smem tile
#define NTILES (K_/KTILE)          // 16
#define CSTRIDE 576                // bytes per code row in smem (512 data + 64 pad)
#define TILE_SM (KTILE*CSTRIDE)    // 36864
#define SRC_CODE 512               // bytes per code in global scratch (dense)

// smem layout (dynamic)
#define OFF_SSQ  (2*TILE_SM)            // 73728: 1024 floats
#define OFF_SIDX (OFF_SSQ + 4096)       // 77824: 128 ints
#define SMEM_TOTAL (OFF_SIDX + 512)     // 78336

// scratch: pre-split emb, cell layout [code][s][tg] -> {hi(8s+tg), hi(8s+tg+4), lo(..), lo(..)}
__device__ float4 g_split[K_ * 32];     // 512 KB
__device__ float  g_ssq[K_];

__device__ __forceinline__ u32 smem_u32(const void* p) {
    u32 a;
    asm("{ .reg .u64 t; cvta.to.shared.u64 t, %1; cvt.u32.u64 %0, t; }" : "=r"(a) : "l"(p));
    return a;
}
__device__ __forceinline__ u32 tf32_of(float v) {
    u32 u; asm("cvt.rna.tf32.f32 %0, %1;" : "=r"(u) : "f"(v)); return u;
}
__device__ __forceinline__ void split2(float v, u32& hi, u32& lo) {
    hi = tf32_of(v);
    lo = tf32_of(v - __uint_as_float(hi));   // v-hi exact (Sterbenz)
}
__device__ __forceinline__ void mma_tf32(float& c0, float& c1, float& c2, float& c3,
                                         u32 a0, u32 a1, u32 a2, u32 a3, u32 b0, u32 b1) {
    asm("mma.sync.aligned.m16n8k8.row.col.f32.tf32.tf32.f32 "
        "{%0,%1,%2,%3}, {%4,%5,%6,%7}, {%8,%9}, {%0,%1,%2,%3};"
        : "+f"(c0), "+f"(c1), "+f"(c2), "+f"(c3)
        : "r"(a0), "r"(a1), "r"(a2), "r"(a3), "r"(b0), "r"(b1));
}
__device__ __forceinline__ void cp16(u32 dst, const void* src) {
    asm volatile("cp.async.cg.shared.global [%0], [%1], 16;" :: "r"(dst), "l"(src) : "memory");
}
__device__ __forceinline__ void cp_commit() {
    asm volatile("cp.async.commit_group;" ::: "memory");
}
template <int N> __device__ __forceinline__ void cp_wait() {
    asm volatile("cp.async.wait_group %0;" :: "n"(N) : "memory");
}

// ---- prep kernel 1: split emb into scratch cells ----
__global__ void prep_split(const float* __restrict__ emb) {
    int c = blockIdx.x * 256 + threadIdx.x;       // 0..32767 cells
    int n = c >> 5, r = c & 31;
    int s = r >> 2, tg = r & 3;
    int d1 = 8 * s + tg, d2 = d1 + 4;
    float v1 = emb[d1 * K_ + n];
    float v2 = emb[d2 * K_ + n];
    u32 h1, l1, h2, l2;
    split2(v1, h1, l1);
    split2(v2, h2, l2);
    float4 cell;
    cell.x = __uint_as_float(h1); cell.y = __uint_as_float(h2);
    cell.z = __uint_as_float(l1); cell.w = __uint_as_float(l2);
    g_split[c] = cell;
}
// ---- prep kernel 2: exact fp32 ||e||^2 ----
__global__ void prep_ssq(const float* __restrict__ emb) {
    int n = blockIdx.x * 256 + threadIdx.x;       // 0..1023
    float s = 0.f;
#pragma unroll
    for (int d = 0; d < D_; ++d) { float v = emb[d * K_ + n]; s = fmaf(v, v, s); }
    g_ssq[n] = s;
}

__global__ __launch_bounds__(NT, 2)
void vq_mma_kernel(const float* __restrict__ x, const float* __restrict__ emb,
                   float* __restrict__ out, int out_size)
{
    extern __shared__ __align__(16) char smem[];
    const u32 sbase = smem_u32(smem);
    const int t = threadIdx.x;
    const int w = t >> 5, lane = t & 31;
    const int g = lane >> 2, tg = lane & 3;

    const int n0 = blockIdx.x * PT;
    const int bb = n0 >> 12, rem0 = n0 & 4095;
    const float* xblk = x + bb * (D_ * HW_) + rem0;

    // prefetch tile 0 (8 cells/thread, 16B each)
    {
        const char* src = (const char*)g_split;         // tile 0 at offset 0
#pragma unroll
        for (int i = 0; i < 8; ++i) {
            int cell = t + 256 * i;                      // 0..2047
            int nl = cell >> 5, r = cell & 31;
            cp16(sbase + nl * CSTRIDE + r * 16, src + cell * 16);
        }
        cp_commit();
    }

    // ssq -> smem
    float* ssq_s = (float*)(smem + OFF_SSQ);
#pragma unroll
    for (int i = 0; i < 4; ++i) ssq_s[t + 256 * i] = g_ssq[t + 256 * i];

    // A fragments: this warp's 16 points, split hi/lo. rows {g, g+8}, dims {8s+tg, 8s+tg+4}
    u32 ah[8][4], al[8][4];
    {
        const float* xw = xblk + w * 16;
#pragma unroll
        for (int s = 0; s < 8; ++s) {
            int d1 = 8 * s + tg, d2 = d1 + 4;
            float v00 = xw[d1 * HW_ + g];
            float v10 = xw[d1 * HW_ + g + 8];
            float v01 = xw[d2 * HW_ + g];
            float v11 = xw[d2 * HW_ + g + 8];
            split2(v00, ah[s][0], al[s][0]);
            split2(v10, ah[s][1], al[s][1]);
            split2(v01, ah[s][2], al[s][2]);
            split2(v11, ah[s][3], al[s][3]);
        }
    }

    float best0 = 3.402823e38f, best1 = 3.402823e38f;
    int   bidx0 = 0, bidx1 = 0;

    for (int tile = 0; tile < NTILES; ++tile) {
        const u32 buf = sbase + (tile & 1) * TILE_SM;
        if (tile + 1 < NTILES) {
            const u32  nbuf = sbase + ((tile + 1) & 1) * TILE_SM;
            const char* src = (const char*)g_split + (tile + 1) * (KTILE * SRC_CODE);
#pragma unroll
            for (int i = 0; i < 8; ++i) {
                int cell = t + 256 * i;
                int nl = cell >> 5, r = cell & 31;
                cp16(nbuf + nl * CSTRIDE + r * 16, src + cell * 16);
            }
            cp_commit();
            cp_wait<1>();      // current tile's copy complete
        } else {
            cp_wait<0>();
        }
        __syncthreads();

        const char* bufc = smem + (tile & 1) * TILE_SM;
#pragma unroll 1
        for (int chunk = 0; chunk < 8; ++chunk) {
            // B cells for this thread: code = chunk*8 + g, k-slot tg
            const float4* bp = (const float4*)(bufc + (chunk * 8 + g) * CSTRIDE + tg * 16);
            float chh0 = 0.f, chh1 = 0.f, chh2 = 0.f, chh3 = 0.f;
            float chl0 = 0.f, chl1 = 0.f, chl2 = 0.f, chl3 = 0.f;
            float clh0 = 0.f, clh1 = 0.f, clh2 = 0.f, clh3 = 0.f;
#pragma unroll
            for (int s = 0; s < 8; ++s) {
                float4 bv = bp[s * 4];                    // {hi1,hi2,lo1,lo2}, LDS.128
                u32 bh0 = __float_as_uint(bv.x), bh1 = __float_as_uint(bv.y);
                u32 bl0 = __float_as_uint(bv.z), bl1 = __float_as_uint(bv.w);
                mma_tf32(chh0, chh1, chh2, chh3, ah[s][0], ah[s][1], ah[s][2], ah[s][3], bh0, bh1);
                mma_tf32(chl0, chl1, chl2, chl3, ah[s][0], ah[s][1], ah[s][2], ah[s][3], bl0, bl1);
                mma_tf32(clh0, clh1, clh2, clh3, al[s][0], al[s][1], al[s][2], al[s][3], bh0, bh1);
            }
            // finalize 2 pts x 2 codes: dist = ||e||^2 - 2*dot
            const int kg = tile * KTILE + chunk * 8 + 2 * tg;   // col0; col1 = kg+1
            const float sq0 = ssq_s[kg], sq1 = ssq_s[kg + 1];
            float d00 = fmaf(-2.f, chh0 + chl0 + clh0, sq0);    // (row g,   col0)
            float d01 = fmaf(-2.f, chh1 + chl1 + clh1, sq1);    // (row g,   col1)
            float d10 = fmaf(-2.f, chh2 + chl2 + clh2, sq0);    // (row g+8, col0)
            float d11 = fmaf(-2.f, chh3 + chl3 + clh3, sq1);    // (row g+8, col1)
            if (d00 < best0) { best0 = d00; bidx0 = kg; }       // ascending codes: strict '<'
            if (d01 < best0) { best0 = d01; bidx0 = kg + 1; }
            if (d10 < best1) { best1 = d10; bidx1 = kg; }
            if (d11 < best1) { best1 = d11; bidx1 = kg + 1; }
        }
        __syncthreads();
    }

    // reduce across the 4 lanes (tg) sharing each point row; tie -> smaller index
#pragma unroll
    for (int mask = 1; mask < 4; mask <<= 1) {
        float e0 = __shfl_xor_sync(0xffffffffu, best0, mask, 4);
        int   j0 = __shfl_xor_sync(0xffffffffu, bidx0, mask, 4);
        if (e0 < best0 || (e0 == best0 && j0 < bidx0)) { best0 = e0; bidx0 = j0; }
        float e1 = __shfl_xor_sync(0xffffffffu, best1, mask, 4);
        int   j1 = __shfl_xor_sync(0xffffffffu, bidx1, mask, 4);
        if (e1 < best1 || (e1 == best1 && j1 < bidx1)) { best1 = e1; bidx1 = j1; }
    }
    int* sidx = (int*)(smem + OFF_SIDX);
    if (tg == 0) {
        sidx[w * 16 + g]     = bidx0;
        sidx[w * 16 + 8 + g] = bidx1;
    }
    __syncthreads();

    if (t < PT && out_size >= RES_ELEMS + NPTS)
        out[RES_ELEMS + n0 + t] = (float)sidx[t];

    // gather winning code vectors (emb L2-hot), coalesced stores
    float* ob = out + bb * (D_ * HW_) + rem0;
#pragma unroll 8
    for (int i = 0; i < 32; ++i) {
        int flat = t + NT * i;
        int p = flat & 127, d = flat >> 7;
        ob[d * HW_ + p] = __ldg(&emb[d * K_ + sidx[p]]);
    }
}

extern "C" void kernel_launch(void* const* d_in, const int* in_sizes, int n_in,
                              void* d_out, int out_size)
{
    const float* x   = (const float*)d_in[0];
    const float* emb = (const float*)d_in[1];
    if (n_in >= 2 && in_sizes[0] == D_ * K_ && in_sizes[1] == RES_ELEMS) {
        x   = (const float*)d_in[1];
        emb = (const float*)d_in[0];
    }
    static int configured = 0;
    if (!configured) {
        cudaFuncSetAttribute(vq_mma_kernel, cudaFuncAttributeMaxDynamicSharedMemorySize, SMEM_TOTAL);
        configured = 1;
    }
    prep_split<<<128, 256>>>(emb);
    prep_ssq<<<4, 256>>>(emb);
    vq_mma_kernel<<<NPTS / PT, NT, SMEM_TOTAL>>>(x, emb, (float*)d_out, out_size);
}

// round 10
// speedup vs baseline: 3.8246x; 1.6695x over previous
#include <cuda_runtime.h>
#include <cuda_fp16.h>
#include <cstdint>

// NearestEmbed (VQ) via 2-split fp16 mma.sync m16n8k16 (lo scaled by 2^11).
// R10: race-free double buffering — barrier BEFORE prefetch issue, so all
// readers of the target buffer are provably done (R7-R9 raced).
// x [32,64,64,64] f32, emb [64,1024] f32
// out = [ result (8388608 f32) | argmin (131072 as f32, if room) ]

typedef uint32_t u32;

#define B_    32
#define D_    64
#define K_    1024
#define HW_   4096
#define NPTS  (B_*HW_)
#define RES_ELEMS (B_*D_*HW_)

#define NT     256
#define PT     128                  // points per block
#define KTILE  128                  // codes per smem tile
#define NTILES (K_/KTILE)           // 8
#define CSTRIDE 320                 // bytes/code in smem (256 data + 64 pad)
#define TILE_SM (KTILE*CSTRIDE)     // 40960
#define SRC_CODE 256                // bytes/code in global scratch

#define OFF_SSQ  (2*TILE_SM)        // 81920: 1024 floats
#define OFF_SIDX (OFF_SSQ + 4096)   // 86016: 128 ints
#define SMEM_TOTAL (OFF_SIDX + 512) // 86528

#define LO_SCALE   2048.0f
#define LO_INV     (1.0f/2048.0f)

// scratch cell [code][s][tg]: {h2(h[d0],h[d0+1]), h2(h[d0+8],h[d0+9]),
//                              h2(l'[d0],l'[d0+1]), h2(l'[d0+8],l'[d0+9])}, d0=16s+2tg
__device__ float4 g_split[K_ * 16];  // 256 KB
__device__ float  g_ssq[K_];

__device__ __forceinline__ u32 smem_u32(const void* p) {
    u32 a;
    asm("{ .reg .u64 t; cvta.to.shared.u64 t, %1; cvt.u32.u64 %0, t; }" : "=r"(a) : "l"(p));
    return a;
}
// h = fp16(v); l' = fp16((v-h)*2048)
__device__ __forceinline__ void split_h(float v, __half& h, __half& l) {
    h = __float2half_rn(v);
    l = __float2half_rn((v - __half2float(h)) * LO_SCALE);
}
__device__ __forceinline__ u32 pack_h2(__half a, __half b) {
    __half2 p = __halves2half2(a, b);
    return *(u32*)&p;
}
__device__ __forceinline__ void mma16816(float& c0, float& c1, float& c2, float& c3,
                                         u32 a0, u32 a1, u32 a2, u32 a3, u32 b0, u32 b1) {
    asm("mma.sync.aligned.m16n8k16.row.col.f32.f16.f16.f32 "
        "{%0,%1,%2,%3}, {%4,%5,%6,%7}, {%8,%9}, {%0,%1,%2,%3};"
        : "+f"(c0), "+f"(c1), "+f"(c2), "+f"(c3)
        : "r"(a0), "r"(a1), "r"(a2), "r"(a3), "r"(b0), "r"(b1));
}
__device__ __forceinline__ void cp16(u32 dst, const void* src) {
    asm volatile("cp.async.cg.shared.global [%0], [%1], 16;" :: "r"(dst), "l"(src) : "memory");
}
__device__ __forceinline__ void cp_commit() {
    asm volatile("cp.async.commit_group;" ::: "memory");
}
template <int N> __device__ __forceinline__ void cp_wait() {
    asm volatile("cp.async.wait_group %0;" :: "n"(N) : "memory");
}

// ---- prep: split emb into fp16 hi / scaled-lo cells ----
__global__ void prep_split(const float* __restrict__ emb) {
    int c = blockIdx.x * 256 + threadIdx.x;      // 0..16383 cells
    int n = c >> 4, r = c & 15;
    int s = r >> 2, tg = r & 3;
    int d0 = 16 * s + 2 * tg;
    float v0 = emb[(d0    ) * K_ + n];
    float v1 = emb[(d0 + 1) * K_ + n];
    float v8 = emb[(d0 + 8) * K_ + n];
    float v9 = emb[(d0 + 9) * K_ + n];
    __half h0, l0, h1, l1, h8, l8, h9, l9;
    split_h(v0, h0, l0); split_h(v1, h1, l1);
    split_h(v8, h8, l8); split_h(v9, h9, l9);
    float4 cell;
    cell.x = __uint_as_float(pack_h2(h0, h1));
    cell.y = __uint_as_float(pack_h2(h8, h9));
    cell.z = __uint_as_float(pack_h2(l0, l1));
    cell.w = __uint_as_float(pack_h2(l8, l9));
    g_split[c] = cell;
}
__global__ void prep_ssq(const float* __restrict__ emb) {
    int n = blockIdx.x * 256 + threadIdx.x;
    float s = 0.f;
#pragma unroll
    for (int d = 0; d < D_; ++d) { float v = emb[d * K_ + n]; s = fmaf(v, v, s); }
    g_ssq[n] = s;
}

__global__ __launch_bounds__(NT, 2)
void vq_mma_kernel(const float* __restrict__ x, const float* __restrict__ emb,
                   float* __restrict__ out, int out_size)
{
    extern __shared__ __align__(16) char smem[];
    const u32 sbase = smem_u32(smem);
    const int t = threadIdx.x;
    const int w = t >> 5, lane = t & 31;
    const int g = lane >> 2, tg = lane & 3;

    const int n0 = blockIdx.x * PT;
    const int bb = n0 >> 12, rem0 = n0 & 4095;
    const float* xblk = x + bb * (D_ * HW_) + rem0;

    // prologue: prefetch tile 0 (2048 cells of 16B, 8 per thread)
    {
        const char* src = (const char*)g_split;
#pragma unroll
        for (int i = 0; i < 8; ++i) {
            int cell = t + 256 * i;
            int nl = cell >> 4, r = cell & 15;
            cp16(sbase + nl * CSTRIDE + r * 16, src + cell * 16);
        }
        cp_commit();
    }

    float* ssq_s = (float*)(smem + OFF_SSQ);
#pragma unroll
    for (int i = 0; i < 4; ++i) ssq_s[t + 256 * i] = g_ssq[t + 256 * i];

    // A fragments: 16 pts (rows w*16+g, +8), dims 16s+2tg+{0,1,8,9}, hi + scaled-lo.
    u32 ah[4][4], al[4][4];
    {
        const float* xw = xblk + w * 16;
#pragma unroll
        for (int s = 0; s < 4; ++s) {
            int d0 = 16 * s + 2 * tg;
            float v;
            __half h0a, l0a, h1a, l1a, h8a, l8a, h9a, l9a;    // row g
            __half h0b, l0b, h1b, l1b, h8b, l8b, h9b, l9b;    // row g+8
            v = xw[(d0    ) * HW_ + g];     split_h(v, h0a, l0a);
            v = xw[(d0 + 1) * HW_ + g];     split_h(v, h1a, l1a);
            v = xw[(d0 + 8) * HW_ + g];     split_h(v, h8a, l8a);
            v = xw[(d0 + 9) * HW_ + g];     split_h(v, h9a, l9a);
            v = xw[(d0    ) * HW_ + g + 8]; split_h(v, h0b, l0b);
            v = xw[(d0 + 1) * HW_ + g + 8]; split_h(v, h1b, l1b);
            v = xw[(d0 + 8) * HW_ + g + 8]; split_h(v, h8b, l8b);
            v = xw[(d0 + 9) * HW_ + g + 8]; split_h(v, h9b, l9b);
            ah[s][0] = pack_h2(h0a, h1a);  ah[s][1] = pack_h2(h0b, h1b);
            ah[s][2] = pack_h2(h8a, h9a);  ah[s][3] = pack_h2(h8b, h9b);
            al[s][0] = pack_h2(l0a, l1a);  al[s][1] = pack_h2(l0b, l1b);
            al[s][2] = pack_h2(l8a, l9a);  al[s][3] = pack_h2(l8b, l9b);
        }
    }

    float best0 = 3.402823e38f, best1 = 3.402823e38f;
    int   bidx0 = 0, bidx1 = 0;

    for (int tile = 0; tile < NTILES; ++tile) {
        cp_wait<0>();      // this tile's data fully landed (issued a full tile ago)
        __syncthreads();   // + all warps done reading the OTHER buffer (prev compute)

        // prefetch tile+1 into the other buffer — all its readers provably done
        if (tile + 1 < NTILES) {
            const u32  nbuf = sbase + ((tile + 1) & 1) * TILE_SM;
            const char* src = (const char*)g_split + (tile + 1) * (KTILE * SRC_CODE);
#pragma unroll
            for (int i = 0; i < 8; ++i) {
                int cell = t + 256 * i;
                int nl = cell >> 4, r = cell & 15;
                cp16(nbuf + nl * CSTRIDE + r * 16, src + cell * 16);
            }
            cp_commit();
        }

        const char* bufc = smem + (tile & 1) * TILE_SM;
#pragma unroll 2
        for (int chunk = 0; chunk < 16; ++chunk) {
            const float4* bp = (const float4*)(bufc + (chunk * 8 + g) * CSTRIDE + tg * 16);
            float chh0 = 0.f, chh1 = 0.f, chh2 = 0.f, chh3 = 0.f;
            float chl0 = 0.f, chl1 = 0.f, chl2 = 0.f, chl3 = 0.f;
            float clh0 = 0.f, clh1 = 0.f, clh2 = 0.f, clh3 = 0.f;
#pragma unroll
            for (int s = 0; s < 4; ++s) {
                float4 bv = bp[s * 4];                    // LDS.128, conflict-free
                u32 bh0 = __float_as_uint(bv.x), bh1 = __float_as_uint(bv.y);
                u32 bl0 = __float_as_uint(bv.z), bl1 = __float_as_uint(bv.w);
                mma16816(chh0, chh1, chh2, chh3, ah[s][0], ah[s][1], ah[s][2], ah[s][3], bh0, bh1);
                mma16816(chl0, chl1, chl2, chl3, ah[s][0], ah[s][1], ah[s][2], ah[s][3], bl0, bl1);
                mma16816(clh0, clh1, clh2, clh3, al[s][0], al[s][1], al[s][2], al[s][3], bh0, bh1);
            }
            const int kg = tile * KTILE + chunk * 8 + 2 * tg;
            const float sq0 = ssq_s[kg], sq1 = ssq_s[kg + 1];
            // dot = hh + (h*l' + l'*h) * 2^-11
            float d00 = fmaf(-2.f, chh0 + (chl0 + clh0) * LO_INV, sq0);  // (row g,   col kg)
            float d01 = fmaf(-2.f, chh1 + (chl1 + clh1) * LO_INV, sq1);  // (row g,   col kg+1)
            float d10 = fmaf(-2.f, chh2 + (chl2 + clh2) * LO_INV, sq0);  // (row g+8, col kg)
            float d11 = fmaf(-2.f, chh3 + (chl3 + clh3) * LO_INV, sq1);  // (row g+8, col kg+1)
            if (d00 < best0) { best0 = d00; bidx0 = kg; }   // ascending codes: strict '<'
            if (d01 < best0) { best0 = d01; bidx0 = kg + 1; }
            if (d10 < best1) { best1 = d10; bidx1 = kg; }
            if (d11 < best1) { best1 = d11; bidx1 = kg + 1; }
        }
    }

    // reduce across the 4 tg-lanes sharing each point row; ties -> smaller index
#pragma unroll
    for (int mask = 1; mask < 4; mask <<= 1) {
        float e0 = __shfl_xor_sync(0xffffffffu, best0, mask, 4);
        int   j0 = __shfl_xor_sync(0xffffffffu, bidx0, mask, 4);
        if (e0 < best0 || (e0 == best0 && j0 < bidx0)) { best0 = e0; bidx0 = j0; }
        float e1 = __shfl_xor_sync(0xffffffffu, best1, mask, 4);
        int   j1 = __shfl_xor_sync(0xffffffffu, bidx1, mask, 4);
        if (e1 < best1 || (e1 == best1 && j1 < bidx1)) { best1 = e1; bidx1 = j1; }
    }
    int* sidx = (int*)(smem + OFF_SIDX);
    if (tg == 0) {
        sidx[w * 16 + g]     = bidx0;
        sidx[w * 16 + 8 + g] = bidx1;
    }
    __syncthreads();

    if (t < PT && out_size >= RES_ELEMS + NPTS)
        out[RES_ELEMS + n0 + t] = (float)sidx[t];

    // gather winning code vectors (emb L2-hot), coalesced stores
    float* ob = out + bb * (D_ * HW_) + rem0;
#pragma unroll 8
    for (int i = 0; i < 32; ++i) {
        int flat = t + NT * i;
        int p = flat & 127, d = flat >> 7;
        ob[d * HW_ + p] = __ldg(&emb[d * K_ + sidx[p]]);
    }
}

extern "C" void kernel_launch(void* const* d_in, const int* in_sizes, int n_in,
                              void* d_out, int out_size)
{
    const float* x   = (const float*)d_in[0];
    const float* emb = (const float*)d_in[1];
    if (n_in >= 2 && in_sizes[0] == D_ * K_ && in_sizes[1] == RES_ELEMS) {
        x   = (const float*)d_in[1];
        emb = (const float*)d_in[0];
    }
    static int configured = 0;
    if (!configured) {
        cudaFuncSetAttribute(vq_mma_kernel, cudaFuncAttributeMaxDynamicSharedMemorySize, SMEM_TOTAL);
        configured = 1;
    }
    prep_split<<<64, 256>>>(emb);
    prep_ssq<<<4, 256>>>(emb);
    vq_mma_kernel<<<NPTS / PT, NT, SMEM_TOTAL>>>(x, emb, (float*)d_out, out_size);
}